// round 1
// baseline (speedup 1.0000x reference)
#include <cuda_runtime.h>

#define COLS 8192
#define GROUPS 32
#define ROWS 1024
#define SCALE 0.75f

// Scratch for the group-summed weight vector (no allocation allowed).
__device__ float g_wtotal[COLS];

// Kernel 1: w_total[i] = sum_g wsums[g][i]
__global__ void reduce_w_kernel(const float* __restrict__ wsums) {
    int i = blockIdx.x * blockDim.x + threadIdx.x;
    if (i >= COLS) return;
    float s = 0.0f;
#pragma unroll
    for (int g = 0; g < GROUPS; ++g) {
        s += wsums[g * COLS + i];
    }
    g_wtotal[i] = s;
}

// Kernel 2: out[row] = SCALE * dot(x[row], w_total)
// One block per row, 256 threads, float4 vectorized loads (8 per thread).
__global__ __launch_bounds__(256) void dot_rows_kernel(const float* __restrict__ x,
                                                       float* __restrict__ out) {
    const int row = blockIdx.x;
    const float4* __restrict__ xr = reinterpret_cast<const float4*>(x + (size_t)row * COLS);
    const float4* __restrict__ wr = reinterpret_cast<const float4*>(g_wtotal);

    float s = 0.0f;
#pragma unroll
    for (int it = 0; it < (COLS / 4) / 256; ++it) {
        int i = it * 256 + threadIdx.x;
        float4 a = xr[i];
        float4 b = wr[i];
        s = fmaf(a.x, b.x, s);
        s = fmaf(a.y, b.y, s);
        s = fmaf(a.z, b.z, s);
        s = fmaf(a.w, b.w, s);
    }

    // warp reduce
#pragma unroll
    for (int o = 16; o > 0; o >>= 1)
        s += __shfl_xor_sync(0xFFFFFFFFu, s, o);

    __shared__ float sm[8];
    if ((threadIdx.x & 31) == 0) sm[threadIdx.x >> 5] = s;
    __syncthreads();

    if (threadIdx.x < 8) {
        s = sm[threadIdx.x];
#pragma unroll
        for (int o = 4; o > 0; o >>= 1)
            s += __shfl_xor_sync(0xFFu, s, o);
        if (threadIdx.x == 0) out[row] = s * SCALE;
    }
}

extern "C" void kernel_launch(void* const* d_in, const int* in_sizes, int n_in,
                              void* d_out, int out_size) {
    const float* x     = (const float*)d_in[0];  // [1024, 8192] f32
    const float* wsums = (const float*)d_in[1];  // [32, 8192] f32
    float* out         = (float*)d_out;          // [1024, 1] f32

    reduce_w_kernel<<<COLS / 256, 256>>>(wsums);
    dot_rows_kernel<<<ROWS, 256>>>(x, out);
}

// round 2
// speedup vs baseline: 1.0029x; 1.0029x over previous
#include <cuda_runtime.h>

#define COLS 8192
#define GROUPS 32
#define ROWS 1024
#define SCALE 0.75f

// Scratch for the group-summed weight vector (no allocation allowed).
__device__ float g_wtotal[COLS];

// Kernel 1: w_total[c] = sum_g wsums[g][c]
// 128 blocks x 256 threads. Each block owns 64 columns; threads are
// (group-chunk, column) pairs: chunk = tid/64 (4 chunks of 8 groups),
// col = tid%64. Each thread sums 8 group values (8 independent LDGs,
// coalesced across the 64 columns), then a shared-memory combine of the
// 4 chunks finishes the column.
__global__ __launch_bounds__(256) void reduce_w_kernel(const float* __restrict__ wsums) {
    const int colbase = blockIdx.x * 64;
    const int lcol  = threadIdx.x & 63;
    const int chunk = threadIdx.x >> 6;          // 0..3
    const int col   = colbase + lcol;

    float s = 0.0f;
#pragma unroll
    for (int g = 0; g < 8; ++g) {
        s += wsums[(chunk * 8 + g) * COLS + col];
    }

    __shared__ float sm[4][64];
    sm[chunk][lcol] = s;
    __syncthreads();

    if (threadIdx.x < 64) {
        g_wtotal[col] = sm[0][lcol] + sm[1][lcol] + sm[2][lcol] + sm[3][lcol];
    }
}

// Kernel 2: out[row] = SCALE * dot(x[row], w_total)
// One block per row, 256 threads. All 8 x float4 loads are batched into
// a register array BEFORE any consumption (MLP_p1 = 8), then the w loads
// (L2-hot, 32 KB) stream through 4 independent accumulators.
__global__ __launch_bounds__(256) void dot_rows_kernel(const float* __restrict__ x,
                                                       float* __restrict__ out) {
    const int row = blockIdx.x;
    const float4* __restrict__ xr = reinterpret_cast<const float4*>(x + (size_t)row * COLS);
    const float4* __restrict__ wr = reinterpret_cast<const float4*>(g_wtotal);

    // Batch all x loads (DRAM tier) up front — 8 outstanding LDG.128 per thread.
    float4 a[8];
#pragma unroll
    for (int i = 0; i < 8; ++i) {
        a[i] = xr[i * 256 + threadIdx.x];
    }

    // w loads are L2 hits; 4 independent accumulators break the FMA chain.
    float s0 = 0.0f, s1 = 0.0f, s2 = 0.0f, s3 = 0.0f;
#pragma unroll
    for (int i = 0; i < 8; i += 4) {
        float4 b0 = wr[(i + 0) * 256 + threadIdx.x];
        float4 b1 = wr[(i + 1) * 256 + threadIdx.x];
        float4 b2 = wr[(i + 2) * 256 + threadIdx.x];
        float4 b3 = wr[(i + 3) * 256 + threadIdx.x];
        s0 = fmaf(a[i + 0].x, b0.x, s0); s0 = fmaf(a[i + 0].y, b0.y, s0);
        s0 = fmaf(a[i + 0].z, b0.z, s0); s0 = fmaf(a[i + 0].w, b0.w, s0);
        s1 = fmaf(a[i + 1].x, b1.x, s1); s1 = fmaf(a[i + 1].y, b1.y, s1);
        s1 = fmaf(a[i + 1].z, b1.z, s1); s1 = fmaf(a[i + 1].w, b1.w, s1);
        s2 = fmaf(a[i + 2].x, b2.x, s2); s2 = fmaf(a[i + 2].y, b2.y, s2);
        s2 = fmaf(a[i + 2].z, b2.z, s2); s2 = fmaf(a[i + 2].w, b2.w, s2);
        s3 = fmaf(a[i + 3].x, b3.x, s3); s3 = fmaf(a[i + 3].y, b3.y, s3);
        s3 = fmaf(a[i + 3].z, b3.z, s3); s3 = fmaf(a[i + 3].w, b3.w, s3);
    }
    float s = (s0 + s1) + (s2 + s3);

    // warp reduce
#pragma unroll
    for (int o = 16; o > 0; o >>= 1)
        s += __shfl_xor_sync(0xFFFFFFFFu, s, o);

    __shared__ float sm[8];
    if ((threadIdx.x & 31) == 0) sm[threadIdx.x >> 5] = s;
    __syncthreads();

    if (threadIdx.x < 8) {
        s = sm[threadIdx.x];
#pragma unroll
        for (int o = 4; o > 0; o >>= 1)
            s += __shfl_xor_sync(0xFFu, s, o);
        if (threadIdx.x == 0) out[row] = s * SCALE;
    }
}

extern "C" void kernel_launch(void* const* d_in, const int* in_sizes, int n_in,
                              void* d_out, int out_size) {
    const float* x     = (const float*)d_in[0];  // [1024, 8192] f32
    const float* wsums = (const float*)d_in[1];  // [32, 8192] f32
    float* out         = (float*)d_out;          // [1024, 1] f32

    reduce_w_kernel<<<COLS / 64, 256>>>(wsums);
    dot_rows_kernel<<<ROWS, 256>>>(x, out);
}